// round 4
// baseline (speedup 1.0000x reference)
#include <cuda_runtime.h>
#include <cstdint>

// LanczosInterpolationLayer: x f32 [32,3,512,512] -> Lanczos4 2x upsample ->
// per-image range renormalize -> *255 -> uint8 (SATURATING trunc) -> f32 out.
//
// Cast model (confirmed R3: rel_err 0.743 == wrap-vs-saturate fingerprint on
// the 18% cohort in (256,265]): u8 = clamp(trunc(f), 0, 255).
//
// Pass 1 (WRITE=false): fused separable resize per 128x64 output tile,
//   block min/max reduce, per-image sortable-uint atomics.
// Pass 2 (WRITE=true): identical recompute + renormalize + saturating
//   quantize, store float32.

#define NIMG   32
#define NCH    96
#define IN_SZ  512
#define OUT_SZ 1024
#define TILE_W 64           // output cols per block
#define TILE_H 128          // output rows per block
#define PAT_W  40           // input patch cols (32 + 8 halo)
#define PAT_H  72           // input patch rows (64 + 8 halo)
#define PSTR   41           // smem stride (odd -> conflict-free)
#define USTR   129          // transposed intermediate stride (odd)

__device__ unsigned g_mn[NIMG];
__device__ unsigned g_mx[NIMG];

static __device__ __forceinline__ unsigned encf(float f) {
    unsigned u = __float_as_uint(f);
    return (u & 0x80000000u) ? ~u : (u | 0x80000000u);
}
static __device__ __forceinline__ float decf(unsigned e) {
    return (e & 0x80000000u) ? __uint_as_float(e ^ 0x80000000u)
                             : __uint_as_float(~e);
}

__global__ void k_init() {
    int i = threadIdx.x;
    if (i < NIMG) {
        g_mn[i] = 0xFFFFFFFFu;  // identity for atomicMin
        g_mx[i] = 0u;           // identity for atomicMax
    }
}

// Normalized Lanczos4 weights, even phase (output 2m): tap j hits input m-4+j.
#define WE0 (-0.0039706f)
#define WE1 ( 0.0314676f)
#define WE2 (-0.0916620f)
#define WE3 ( 0.2826868f)
#define WE4 ( 0.8933939f)
#define WE5 (-0.1523043f)
#define WE6 ( 0.0554435f)
#define WE7 (-0.0150549f)

// even output 2m: window rows m..m+7 in a0..a7
#define EVEN8(a0,a1,a2,a3,a4,a5,a6,a7) \
  fmaf((a7), WE7, fmaf((a6), WE6, fmaf((a5), WE5, fmaf((a4), WE4, \
  fmaf((a3), WE3, fmaf((a2), WE2, fmaf((a1), WE1, (a0) * WE0)))))))
// odd output 2m+1: rows m-3..m+4 in a1..a8, weights reversed
#define ODD8(a1,a2,a3,a4,a5,a6,a7,a8) \
  fmaf((a8), WE0, fmaf((a7), WE1, fmaf((a6), WE2, fmaf((a5), WE3, \
  fmaf((a4), WE4, fmaf((a3), WE5, fmaf((a2), WE6, (a1) * WE7)))))))

template <bool WRITE>
__global__ void __launch_bounds__(256)
k_resize(const float* __restrict__ x, float* __restrict__ out)
{
    __shared__ float s_in[PAT_H * PSTR];   // input patch  [row][col]
    __shared__ float s_ut[PAT_W * USTR];   // H-resampled, transposed [icol][orow]
    __shared__ float s_red[16];

    const int tid = threadIdx.x;
    const int bc  = blockIdx.z;                  // image*3 + channel
    const int m0  = blockIdx.y * (TILE_H / 2);   // input row base
    const int n0  = blockIdx.x * (TILE_W / 2);   // input col base
    const float* src = x + (size_t)bc * (IN_SZ * IN_SZ);

    // ---- stage A: load input patch with replicate border ----
    for (int idx = tid; idx < PAT_H * PAT_W; idx += 256) {
        int r = idx / PAT_W;
        int c = idx - r * PAT_W;
        int gy = min(max(m0 - 4 + r, 0), IN_SZ - 1);
        int gx = min(max(n0 - 4 + c, 0), IN_SZ - 1);
        s_in[r * PSTR + c] = src[gy * IN_SZ + gx];
    }
    __syncthreads();

    // ---- stage B: vertical (height) resample, write transposed ----
    for (int t = tid; t < PAT_W * 8; t += 256) {
        int g  = t / PAT_W;
        int ic = t - g * PAT_W;
        int mb = g * 8;
        const float* p = &s_in[mb * PSTR + ic];
        float w0 = p[0 * PSTR], w1 = p[1 * PSTR], w2 = p[2 * PSTR];
        float w3 = p[3 * PSTR], w4 = p[4 * PSTR], w5 = p[5 * PSTR];
        float w6 = p[6 * PSTR], w7 = p[7 * PSTR], w8 = p[8 * PSTR];
        float* q = &s_ut[ic * USTR + 2 * mb];
        #pragma unroll
        for (int mm = 0; mm < 8; mm++) {
            q[2 * mm]     = EVEN8(w0, w1, w2, w3, w4, w5, w6, w7);
            q[2 * mm + 1] = ODD8(w1, w2, w3, w4, w5, w6, w7, w8);
            w0 = w1; w1 = w2; w2 = w3; w3 = w4;
            w4 = w5; w5 = w6; w6 = w7; w7 = w8;
            if (mm < 7) w8 = p[(mm + 9) * PSTR];
        }
    }
    __syncthreads();

    // ---- stage C: horizontal (width) resample + reduce / renorm+store ----
    const int orr = tid & (TILE_H - 1);   // output row within tile
    const int h   = tid >> 7;             // column half (0,1)

    float win[9];
    #pragma unroll
    for (int j = 0; j < 9; j++) win[j] = s_ut[(16 * h + j) * USTR + orr];

    float vmin = __int_as_float(0x7f800000);
    float vmax = -vmin;

    float s1 = 0.f, s2 = 0.f, c1 = 0.f, c2 = 0.f;
    bool  doNorm = false;
    const float ubt = -10.0f / 255.0f;
    if (WRITE) {
        int img = bc / 3;
        float mn = decf(g_mn[img]);
        float mx = decf(g_mx[img]);
        doNorm = (mx - mn) > 1.0f;
        float otr = mx - 1.0f;
        s1 = (1.0f / 255.0f) / (otr != 0.0f ? otr : 1.0f);
        s2 = ubt / (mn != 0.0f ? mn : 1.0f);
        c1 = 1.0f - 1.0f / 255.0f;
        c2 = 1.0f - ubt;
    }

    float res[32];
    #pragma unroll
    for (int n = 0; n < 16; n++) {
        float e = EVEN8(win[0], win[1], win[2], win[3], win[4], win[5], win[6], win[7]);
        float o = ODD8 (win[1], win[2], win[3], win[4], win[5], win[6], win[7], win[8]);
        if (!WRITE) {
            vmin = fminf(vmin, fminf(e, o));
            vmax = fmaxf(vmax, fmaxf(e, o));
        } else {
            float v1e = (e > 1.0f) ? fmaf(e - 1.0f, s1, c1) : ((e < 1.0f) ? e * c1 : e);
            float v2e = (v1e < 0.0f) ? fmaf(v1e, s2, ubt) : ((v1e > 0.0f) ? v1e * c2 : v1e);
            float fe  = (doNorm ? v2e : e) * 255.0f;
            float v1o = (o > 1.0f) ? fmaf(o - 1.0f, s1, c1) : ((o < 1.0f) ? o * c1 : o);
            float v2o = (v1o < 0.0f) ? fmaf(v1o, s2, ubt) : ((v1o > 0.0f) ? v1o * c2 : v1o);
            float fo  = (doNorm ? v2o : o) * 255.0f;
            // uint8 semantics: saturating truncation (cvt.rzi.u32 clamps
            // negatives to 0; fminf clamps the 256..265 tail to 255)
            res[2 * n]     = (float)__float2uint_rz(fminf(fe, 255.0f));
            res[2 * n + 1] = (float)__float2uint_rz(fminf(fo, 255.0f));
        }
        #pragma unroll
        for (int j = 0; j < 8; j++) win[j] = win[j + 1];
        if (n < 15) win[8] = s_ut[(16 * h + 9 + n) * USTR + orr];
    }

    if (!WRITE) {
        #pragma unroll
        for (int m = 16; m; m >>= 1) {
            vmin = fminf(vmin, __shfl_xor_sync(0xffffffffu, vmin, m));
            vmax = fmaxf(vmax, __shfl_xor_sync(0xffffffffu, vmax, m));
        }
        int w = tid >> 5, l = tid & 31;
        if (l == 0) { s_red[w] = vmin; s_red[8 + w] = vmax; }
        __syncthreads();
        if (tid == 0) {
            float a = s_red[0], b = s_red[8];
            #pragma unroll
            for (int i = 1; i < 8; i++) {
                a = fminf(a, s_red[i]);
                b = fmaxf(b, s_red[8 + i]);
            }
            int img = bc / 3;
            atomicMin(&g_mn[img], encf(a));
            atomicMax(&g_mx[img], encf(b));
        }
    } else {
        size_t row = (size_t)(blockIdx.y * TILE_H + orr);
        float* dst = out + ((size_t)bc * OUT_SZ + row) * OUT_SZ
                   + blockIdx.x * TILE_W + h * 32;
        #pragma unroll
        for (int q = 0; q < 8; q++) {
            *reinterpret_cast<float4*>(dst + 4 * q) =
                make_float4(res[4 * q], res[4 * q + 1], res[4 * q + 2], res[4 * q + 3]);
        }
    }
}

extern "C" void kernel_launch(void* const* d_in, const int* in_sizes, int n_in,
                              void* d_out, int out_size)
{
    const float* x = (const float*)d_in[0];
    float* out = (float*)d_out;

    k_init<<<1, 32>>>();
    dim3 grid(OUT_SZ / TILE_W, OUT_SZ / TILE_H, NCH);
    k_resize<false><<<grid, 256>>>(x, nullptr);
    k_resize<true ><<<grid, 256>>>(x, out);
}

// round 5
// speedup vs baseline: 1.3682x; 1.3682x over previous
#include <cuda_runtime.h>
#include <cstdint>

// LanczosInterpolationLayer: x f32 [32,3,512,512] -> Lanczos4 2x upsample ->
// per-image range renormalize -> *255 -> uint8 (saturating trunc) -> f32 out.
//
// R4: passed at 356us with ~2 CTA/SM (res[32] register pressure). This rev:
//  - streaming float4 stores (no res[] buffer), __launch_bounds__(256,4)
//  - renorm collapsed to 3 precomputed affine segments
//  - stage-A loads as fixed 12-step predicated unroll (MLP)

#define NIMG   32
#define NCH    96
#define IN_SZ  512
#define OUT_SZ 1024
#define TILE_W 64           // output cols per block
#define TILE_H 128          // output rows per block
#define PAT_W  40           // input patch cols (32 + 8 halo)
#define PAT_H  72           // input patch rows (64 + 8 halo)
#define PSTR   41           // smem stride (odd -> conflict-free)
#define USTR   129          // transposed intermediate stride (odd)

__device__ unsigned g_mn[NIMG];
__device__ unsigned g_mx[NIMG];

static __device__ __forceinline__ unsigned encf(float f) {
    unsigned u = __float_as_uint(f);
    return (u & 0x80000000u) ? ~u : (u | 0x80000000u);
}
static __device__ __forceinline__ float decf(unsigned e) {
    return (e & 0x80000000u) ? __uint_as_float(e ^ 0x80000000u)
                             : __uint_as_float(~e);
}

__global__ void k_init() {
    int i = threadIdx.x;
    if (i < NIMG) {
        g_mn[i] = 0xFFFFFFFFu;  // identity for atomicMin
        g_mx[i] = 0u;           // identity for atomicMax
    }
}

// Normalized Lanczos4 weights, even phase (output 2m): tap j hits input m-4+j.
#define WE0 (-0.0039706f)
#define WE1 ( 0.0314676f)
#define WE2 (-0.0916620f)
#define WE3 ( 0.2826868f)
#define WE4 ( 0.8933939f)
#define WE5 (-0.1523043f)
#define WE6 ( 0.0554435f)
#define WE7 (-0.0150549f)

// even output 2m: window rows m..m+7 in a0..a7
#define EVEN8(a0,a1,a2,a3,a4,a5,a6,a7) \
  fmaf((a7), WE7, fmaf((a6), WE6, fmaf((a5), WE5, fmaf((a4), WE4, \
  fmaf((a3), WE3, fmaf((a2), WE2, fmaf((a1), WE1, (a0) * WE0)))))))
// odd output 2m+1: rows m-3..m+4 in a1..a8, weights reversed
#define ODD8(a1,a2,a3,a4,a5,a6,a7,a8) \
  fmaf((a8), WE0, fmaf((a7), WE1, fmaf((a6), WE2, fmaf((a5), WE3, \
  fmaf((a4), WE4, fmaf((a3), WE5, fmaf((a2), WE6, (a1) * WE7)))))))

template <bool WRITE>
__global__ void __launch_bounds__(256, 4)
k_resize(const float* __restrict__ x, float* __restrict__ out)
{
    __shared__ float s_in[PAT_H * PSTR];   // input patch  [row][col]
    __shared__ float s_ut[PAT_W * USTR];   // H-resampled, transposed [icol][orow]
    __shared__ float s_red[16];

    const int tid = threadIdx.x;
    const int bc  = blockIdx.z;                  // image*3 + channel
    const int m0  = blockIdx.y * (TILE_H / 2);   // input row base
    const int n0  = blockIdx.x * (TILE_W / 2);   // input col base
    const float* src = x + (size_t)bc * (IN_SZ * IN_SZ);

    // ---- stage A: load input patch with replicate border ----
    #pragma unroll
    for (int i = 0; i < 12; i++) {
        int idx = tid + 256 * i;
        if (idx < PAT_H * PAT_W) {
            int r = idx / PAT_W;
            int c = idx - r * PAT_W;
            int gy = min(max(m0 - 4 + r, 0), IN_SZ - 1);
            int gx = min(max(n0 - 4 + c, 0), IN_SZ - 1);
            s_in[r * PSTR + c] = src[gy * IN_SZ + gx];
        }
    }
    __syncthreads();

    // ---- stage B: vertical (height) resample, write transposed ----
    for (int t = tid; t < PAT_W * 8; t += 256) {
        int g  = t / PAT_W;
        int ic = t - g * PAT_W;
        int mb = g * 8;
        const float* p = &s_in[mb * PSTR + ic];
        float w0 = p[0 * PSTR], w1 = p[1 * PSTR], w2 = p[2 * PSTR];
        float w3 = p[3 * PSTR], w4 = p[4 * PSTR], w5 = p[5 * PSTR];
        float w6 = p[6 * PSTR], w7 = p[7 * PSTR], w8 = p[8 * PSTR];
        float* q = &s_ut[ic * USTR + 2 * mb];
        #pragma unroll
        for (int mm = 0; mm < 8; mm++) {
            q[2 * mm]     = EVEN8(w0, w1, w2, w3, w4, w5, w6, w7);
            q[2 * mm + 1] = ODD8(w1, w2, w3, w4, w5, w6, w7, w8);
            w0 = w1; w1 = w2; w2 = w3; w3 = w4;
            w4 = w5; w5 = w6; w6 = w7; w7 = w8;
            if (mm < 7) w8 = p[(mm + 9) * PSTR];
        }
    }
    __syncthreads();

    // ---- stage C: horizontal (width) resample + reduce / renorm+store ----
    const int orr = tid & (TILE_H - 1);   // output row within tile
    const int h   = tid >> 7;             // column half (0,1)

    float win[9];
    #pragma unroll
    for (int j = 0; j < 9; j++) win[j] = s_ut[(16 * h + j) * USTR + orr];

    float vmin = __int_as_float(0x7f800000);
    float vmax = -vmin;

    // renorm as 3 affine segments (times 255), selected per pixel:
    //   v < 0      : P2*v + Q2
    //   0 <= v <= 1: P1*v
    //   v > 1      : P3*v + Q3
    float P1 = 255.f, P2 = 255.f, P3 = 255.f, Q2 = 0.f, Q3 = 0.f;
    float* dst = nullptr;
    if (WRITE) {
        int img = bc / 3;
        float mn = decf(g_mn[img]);
        float mx = decf(g_mx[img]);
        bool doNorm = (mx - mn) > 1.0f;
        if (doNorm) {
            const float ott = 1.0f / 255.0f;
            const float ubt = -10.0f / 255.0f;
            float otr = mx - 1.0f;
            float s1 = ott / (otr != 0.0f ? otr : 1.0f);
            float s2 = ubt / (mn != 0.0f ? mn : 1.0f);
            float c1 = 1.0f - ott;
            float c2 = 1.0f - ubt;
            P1 = 255.0f * c1 * c2;
            P2 = 255.0f * c1 * s2;
            Q2 = 255.0f * ubt;
            P3 = 255.0f * s1 * c2;
            Q3 = 255.0f * c2 * (c1 - s1);
        }
        size_t row = (size_t)(blockIdx.y * TILE_H + orr);
        dst = out + ((size_t)bc * OUT_SZ + row) * OUT_SZ
            + blockIdx.x * TILE_W + h * 32;
    }

    float r0 = 0.f, r1 = 0.f;
    #pragma unroll
    for (int n = 0; n < 16; n++) {
        float e = EVEN8(win[0], win[1], win[2], win[3], win[4], win[5], win[6], win[7]);
        float o = ODD8 (win[1], win[2], win[3], win[4], win[5], win[6], win[7], win[8]);
        if (!WRITE) {
            vmin = fminf(vmin, fminf(e, o));
            vmax = fmaxf(vmax, fmaxf(e, o));
        } else {
            float Pe = (e < 0.f) ? P2 : ((e > 1.f) ? P3 : P1);
            float Qe = (e < 0.f) ? Q2 : ((e > 1.f) ? Q3 : 0.f);
            float Po = (o < 0.f) ? P2 : ((o > 1.f) ? P3 : P1);
            float Qo = (o < 0.f) ? Q2 : ((o > 1.f) ? Q3 : 0.f);
            // saturating uint8 quantize (cvt.rzi.u32 clamps negatives to 0)
            float fe = (float)__float2uint_rz(fminf(fmaf(e, Pe, Qe), 255.0f));
            float fo = (float)__float2uint_rz(fminf(fmaf(o, Po, Qo), 255.0f));
            if (n & 1) {
                *reinterpret_cast<float4*>(dst + 2 * (n - 1)) =
                    make_float4(r0, r1, fe, fo);
            } else {
                r0 = fe; r1 = fo;
            }
        }
        #pragma unroll
        for (int j = 0; j < 8; j++) win[j] = win[j + 1];
        if (n < 15) win[8] = s_ut[(16 * h + 9 + n) * USTR + orr];
    }

    if (!WRITE) {
        #pragma unroll
        for (int m = 16; m; m >>= 1) {
            vmin = fminf(vmin, __shfl_xor_sync(0xffffffffu, vmin, m));
            vmax = fmaxf(vmax, __shfl_xor_sync(0xffffffffu, vmax, m));
        }
        int w = tid >> 5, l = tid & 31;
        if (l == 0) { s_red[w] = vmin; s_red[8 + w] = vmax; }
        __syncthreads();
        if (tid == 0) {
            float a = s_red[0], b = s_red[8];
            #pragma unroll
            for (int i = 1; i < 8; i++) {
                a = fminf(a, s_red[i]);
                b = fmaxf(b, s_red[8 + i]);
            }
            int img = bc / 3;
            atomicMin(&g_mn[img], encf(a));
            atomicMax(&g_mx[img], encf(b));
        }
    }
}

extern "C" void kernel_launch(void* const* d_in, const int* in_sizes, int n_in,
                              void* d_out, int out_size)
{
    const float* x = (const float*)d_in[0];
    float* out = (float*)d_out;

    k_init<<<1, 32>>>();
    dim3 grid(OUT_SZ / TILE_W, OUT_SZ / TILE_H, NCH);
    k_resize<false><<<grid, 256>>>(x, nullptr);
    k_resize<true ><<<grid, 256>>>(x, out);
}

// round 6
// speedup vs baseline: 1.3799x; 1.0086x over previous
#include <cuda_runtime.h>
#include <cstdint>

// LanczosInterpolationLayer: x f32 [32,3,512,512] -> Lanczos4 2x upsample ->
// per-image range renormalize -> *255 -> uint8 (saturating trunc) -> f32 out.
//
// R5 (260us): atomic min/max with init kernel, launch_bounds(256,4).
// R6: - k_init removed: pass-1 writes per-block min/max partials (overwritten
//       every replay -> no init), pass-2 reduces 384 partials per image at
//       kernel start (L2-hot, overlapped with stage-A loads).
//     - launch_bounds(256,5) for 5 CTAs/SM.

#define NIMG   32
#define NCH    96
#define IN_SZ  512
#define OUT_SZ 1024
#define TILE_W 64           // output cols per block
#define TILE_H 128          // output rows per block
#define PAT_W  40           // input patch cols (32 + 8 halo)
#define PAT_H  72           // input patch rows (64 + 8 halo)
#define PSTR   41           // smem stride (odd -> conflict-free)
#define USTR   129          // transposed intermediate stride (odd)
#define SLOTS  128          // blocks per channel (16 x * 8 y)

__device__ float g_pmin[NCH * SLOTS];
__device__ float g_pmax[NCH * SLOTS];

// Normalized Lanczos4 weights, even phase (output 2m): tap j hits input m-4+j.
#define WE0 (-0.0039706f)
#define WE1 ( 0.0314676f)
#define WE2 (-0.0916620f)
#define WE3 ( 0.2826868f)
#define WE4 ( 0.8933939f)
#define WE5 (-0.1523043f)
#define WE6 ( 0.0554435f)
#define WE7 (-0.0150549f)

// even output 2m: window rows m..m+7 in a0..a7
#define EVEN8(a0,a1,a2,a3,a4,a5,a6,a7) \
  fmaf((a7), WE7, fmaf((a6), WE6, fmaf((a5), WE5, fmaf((a4), WE4, \
  fmaf((a3), WE3, fmaf((a2), WE2, fmaf((a1), WE1, (a0) * WE0)))))))
// odd output 2m+1: rows m-3..m+4 in a1..a8, weights reversed
#define ODD8(a1,a2,a3,a4,a5,a6,a7,a8) \
  fmaf((a8), WE0, fmaf((a7), WE1, fmaf((a6), WE2, fmaf((a5), WE3, \
  fmaf((a4), WE4, fmaf((a3), WE5, fmaf((a2), WE6, (a1) * WE7)))))))

template <bool WRITE>
__global__ void __launch_bounds__(256, 5)
k_resize(const float* __restrict__ x, float* __restrict__ out)
{
    __shared__ float s_in[PAT_H * PSTR];   // input patch  [row][col]
    __shared__ float s_ut[PAT_W * USTR];   // H-resampled, transposed [icol][orow]
    __shared__ float s_red[16];

    const int tid = threadIdx.x;
    const int bc  = blockIdx.z;                  // image*3 + channel
    const int m0  = blockIdx.y * (TILE_H / 2);   // input row base
    const int n0  = blockIdx.x * (TILE_W / 2);   // input col base
    const float* src = x + (size_t)bc * (IN_SZ * IN_SZ);

    // ---- pass 2 only: reduce this image's 384 min/max partials ----
    // (warp-level here; cross-warp via s_red folded into the stage-A sync)
    if (WRITE) {
        const int img3 = (bc / 3) * 3;
        float a = __int_as_float(0x7f800000);
        float b = -a;
        #pragma unroll
        for (int i = 0; i < 2; i++) {
            int idx = tid + 256 * i;
            if (idx < 3 * SLOTS) {
                a = fminf(a, g_pmin[img3 * SLOTS + idx]);
                b = fmaxf(b, g_pmax[img3 * SLOTS + idx]);
            }
        }
        #pragma unroll
        for (int m = 16; m; m >>= 1) {
            a = fminf(a, __shfl_xor_sync(0xffffffffu, a, m));
            b = fmaxf(b, __shfl_xor_sync(0xffffffffu, b, m));
        }
        if ((tid & 31) == 0) {
            s_red[tid >> 5]       = a;
            s_red[8 + (tid >> 5)] = b;
        }
    }

    // ---- stage A: load input patch with replicate border ----
    #pragma unroll
    for (int i = 0; i < 12; i++) {
        int idx = tid + 256 * i;
        if (idx < PAT_H * PAT_W) {
            int r = idx / PAT_W;
            int c = idx - r * PAT_W;
            int gy = min(max(m0 - 4 + r, 0), IN_SZ - 1);
            int gx = min(max(n0 - 4 + c, 0), IN_SZ - 1);
            s_in[r * PSTR + c] = src[gy * IN_SZ + gx];
        }
    }
    __syncthreads();

    // renorm as 3 affine segments (times 255), selected per pixel:
    //   v < 0 : P2*v + Q2 ; 0 <= v <= 1 : P1*v ; v > 1 : P3*v + Q3
    float P1 = 255.f, P2 = 255.f, P3 = 255.f, Q2 = 0.f, Q3 = 0.f;
    if (WRITE) {
        float mn = s_red[0], mx = s_red[8];
        #pragma unroll
        for (int i = 1; i < 8; i++) {
            mn = fminf(mn, s_red[i]);
            mx = fmaxf(mx, s_red[8 + i]);
        }
        if ((mx - mn) > 1.0f) {
            const float ott = 1.0f / 255.0f;
            const float ubt = -10.0f / 255.0f;
            float otr = mx - 1.0f;
            float s1 = ott / (otr != 0.0f ? otr : 1.0f);
            float s2 = ubt / (mn != 0.0f ? mn : 1.0f);
            float c1 = 1.0f - ott;
            float c2 = 1.0f - ubt;
            P1 = 255.0f * c1 * c2;
            P2 = 255.0f * c1 * s2;
            Q2 = 255.0f * ubt;
            P3 = 255.0f * s1 * c2;
            Q3 = 255.0f * c2 * (c1 - s1);
        }
    }

    // ---- stage B: vertical (height) resample, write transposed ----
    for (int t = tid; t < PAT_W * 8; t += 256) {
        int g  = t / PAT_W;
        int ic = t - g * PAT_W;
        int mb = g * 8;
        const float* p = &s_in[mb * PSTR + ic];
        float w0 = p[0 * PSTR], w1 = p[1 * PSTR], w2 = p[2 * PSTR];
        float w3 = p[3 * PSTR], w4 = p[4 * PSTR], w5 = p[5 * PSTR];
        float w6 = p[6 * PSTR], w7 = p[7 * PSTR], w8 = p[8 * PSTR];
        float* q = &s_ut[ic * USTR + 2 * mb];
        #pragma unroll
        for (int mm = 0; mm < 8; mm++) {
            q[2 * mm]     = EVEN8(w0, w1, w2, w3, w4, w5, w6, w7);
            q[2 * mm + 1] = ODD8(w1, w2, w3, w4, w5, w6, w7, w8);
            w0 = w1; w1 = w2; w2 = w3; w3 = w4;
            w4 = w5; w5 = w6; w6 = w7; w7 = w8;
            if (mm < 7) w8 = p[(mm + 9) * PSTR];
        }
    }
    __syncthreads();

    // ---- stage C: horizontal (width) resample + reduce / renorm+store ----
    const int orr = tid & (TILE_H - 1);   // output row within tile
    const int h   = tid >> 7;             // column half (0,1)

    float win[9];
    #pragma unroll
    for (int j = 0; j < 9; j++) win[j] = s_ut[(16 * h + j) * USTR + orr];

    float vmin = __int_as_float(0x7f800000);
    float vmax = -vmin;

    float* dst = nullptr;
    if (WRITE) {
        size_t row = (size_t)(blockIdx.y * TILE_H + orr);
        dst = out + ((size_t)bc * OUT_SZ + row) * OUT_SZ
            + blockIdx.x * TILE_W + h * 32;
    }

    float r0 = 0.f, r1 = 0.f;
    #pragma unroll
    for (int n = 0; n < 16; n++) {
        float e = EVEN8(win[0], win[1], win[2], win[3], win[4], win[5], win[6], win[7]);
        float o = ODD8 (win[1], win[2], win[3], win[4], win[5], win[6], win[7], win[8]);
        if (!WRITE) {
            vmin = fminf(vmin, fminf(e, o));
            vmax = fmaxf(vmax, fmaxf(e, o));
        } else {
            float Pe = (e < 0.f) ? P2 : ((e > 1.f) ? P3 : P1);
            float Qe = (e < 0.f) ? Q2 : ((e > 1.f) ? Q3 : 0.f);
            float Po = (o < 0.f) ? P2 : ((o > 1.f) ? P3 : P1);
            float Qo = (o < 0.f) ? Q2 : ((o > 1.f) ? Q3 : 0.f);
            // saturating uint8 quantize (cvt.rzi.u32 clamps negatives to 0)
            float fe = (float)__float2uint_rz(fminf(fmaf(e, Pe, Qe), 255.0f));
            float fo = (float)__float2uint_rz(fminf(fmaf(o, Po, Qo), 255.0f));
            if (n & 1) {
                *reinterpret_cast<float4*>(dst + 2 * (n - 1)) =
                    make_float4(r0, r1, fe, fo);
            } else {
                r0 = fe; r1 = fo;
            }
        }
        #pragma unroll
        for (int j = 0; j < 8; j++) win[j] = win[j + 1];
        if (n < 15) win[8] = s_ut[(16 * h + 9 + n) * USTR + orr];
    }

    if (!WRITE) {
        #pragma unroll
        for (int m = 16; m; m >>= 1) {
            vmin = fminf(vmin, __shfl_xor_sync(0xffffffffu, vmin, m));
            vmax = fmaxf(vmax, __shfl_xor_sync(0xffffffffu, vmax, m));
        }
        int w = tid >> 5, l = tid & 31;
        if (l == 0) { s_red[w] = vmin; s_red[8 + w] = vmax; }
        __syncthreads();
        if (tid == 0) {
            float a = s_red[0], b = s_red[8];
            #pragma unroll
            for (int i = 1; i < 8; i++) {
                a = fminf(a, s_red[i]);
                b = fmaxf(b, s_red[8 + i]);
            }
            int slot = blockIdx.y * 16 + blockIdx.x;
            g_pmin[bc * SLOTS + slot] = a;
            g_pmax[bc * SLOTS + slot] = b;
        }
    }
}

extern "C" void kernel_launch(void* const* d_in, const int* in_sizes, int n_in,
                              void* d_out, int out_size)
{
    const float* x = (const float*)d_in[0];
    float* out = (float*)d_out;

    dim3 grid(OUT_SZ / TILE_W, OUT_SZ / TILE_H, NCH);
    k_resize<false><<<grid, 256>>>(x, nullptr);
    k_resize<true ><<<grid, 256>>>(x, out);
}

// round 7
// speedup vs baseline: 1.3814x; 1.0011x over previous
#include <cuda_runtime.h>
#include <cstdint>

// LanczosInterpolationLayer: x f32 [32,3,512,512] -> Lanczos4 2x upsample ->
// per-image range renormalize -> *255 -> uint8 (saturating trunc) -> f32 out.
//
// R6 (258us): pass2 = 180us, L1 74% / ALU 38% / issue 52% -> latency+issue
// bound in stage C. R7:
//  - stage C: preload full 24-float window upfront (no per-iter LDS dep,
//    no register shifting), fully unrolled 32-output FMA burst.
//  - epilogue: renorm collapsed to f = min(P1*v, P3*v+Q3) (v<0 segment is
//    always <0 -> quantizes to 0 either way; segments cross at v=1).

#define NIMG   32
#define NCH    96
#define IN_SZ  512
#define OUT_SZ 1024
#define TILE_W 64           // output cols per block
#define TILE_H 128          // output rows per block
#define PAT_W  40           // input patch cols (32 + 8 halo)
#define PAT_H  72           // input patch rows (64 + 8 halo)
#define PSTR   41           // smem stride (odd -> conflict-free)
#define USTR   129          // transposed intermediate stride (odd)
#define SLOTS  128          // blocks per channel (16 x * 8 y)

__device__ float g_pmin[NCH * SLOTS];
__device__ float g_pmax[NCH * SLOTS];

// Normalized Lanczos4 weights, even phase (output 2m): tap j hits input m-4+j.
#define WE0 (-0.0039706f)
#define WE1 ( 0.0314676f)
#define WE2 (-0.0916620f)
#define WE3 ( 0.2826868f)
#define WE4 ( 0.8933939f)
#define WE5 (-0.1523043f)
#define WE6 ( 0.0554435f)
#define WE7 (-0.0150549f)

// even output 2m: window rows m..m+7 in a0..a7
#define EVEN8(a0,a1,a2,a3,a4,a5,a6,a7) \
  fmaf((a7), WE7, fmaf((a6), WE6, fmaf((a5), WE5, fmaf((a4), WE4, \
  fmaf((a3), WE3, fmaf((a2), WE2, fmaf((a1), WE1, (a0) * WE0)))))))
// odd output 2m+1: rows m-3..m+4 in a1..a8, weights reversed
#define ODD8(a1,a2,a3,a4,a5,a6,a7,a8) \
  fmaf((a8), WE0, fmaf((a7), WE1, fmaf((a6), WE2, fmaf((a5), WE3, \
  fmaf((a4), WE4, fmaf((a3), WE5, fmaf((a2), WE6, (a1) * WE7)))))))

template <bool WRITE>
__global__ void __launch_bounds__(256, 5)
k_resize(const float* __restrict__ x, float* __restrict__ out)
{
    __shared__ float s_in[PAT_H * PSTR];   // input patch  [row][col]
    __shared__ float s_ut[PAT_W * USTR];   // H-resampled, transposed [icol][orow]
    __shared__ float s_red[16];

    const int tid = threadIdx.x;
    const int bc  = blockIdx.z;                  // image*3 + channel
    const int m0  = blockIdx.y * (TILE_H / 2);   // input row base
    const int n0  = blockIdx.x * (TILE_W / 2);   // input col base
    const float* src = x + (size_t)bc * (IN_SZ * IN_SZ);

    // ---- pass 2 only: reduce this image's 384 min/max partials ----
    if (WRITE) {
        const int img3 = (bc / 3) * 3;
        float a = __int_as_float(0x7f800000);
        float b = -a;
        #pragma unroll
        for (int i = 0; i < 2; i++) {
            int idx = tid + 256 * i;
            if (idx < 3 * SLOTS) {
                a = fminf(a, g_pmin[img3 * SLOTS + idx]);
                b = fmaxf(b, g_pmax[img3 * SLOTS + idx]);
            }
        }
        #pragma unroll
        for (int m = 16; m; m >>= 1) {
            a = fminf(a, __shfl_xor_sync(0xffffffffu, a, m));
            b = fmaxf(b, __shfl_xor_sync(0xffffffffu, b, m));
        }
        if ((tid & 31) == 0) {
            s_red[tid >> 5]       = a;
            s_red[8 + (tid >> 5)] = b;
        }
    }

    // ---- stage A: load input patch with replicate border ----
    #pragma unroll
    for (int i = 0; i < 12; i++) {
        int idx = tid + 256 * i;
        if (idx < PAT_H * PAT_W) {
            int r = idx / PAT_W;
            int c = idx - r * PAT_W;
            int gy = min(max(m0 - 4 + r, 0), IN_SZ - 1);
            int gx = min(max(n0 - 4 + c, 0), IN_SZ - 1);
            s_in[r * PSTR + c] = src[gy * IN_SZ + gx];
        }
    }
    __syncthreads();

    // renorm collapsed: f(v) = min(P1*v, P3*v + Q3), then clamp [0,255]+trunc.
    float P1 = 255.f, P3 = 255.f, Q3 = 0.f;
    if (WRITE) {
        float mn = s_red[0], mx = s_red[8];
        #pragma unroll
        for (int i = 1; i < 8; i++) {
            mn = fminf(mn, s_red[i]);
            mx = fmaxf(mx, s_red[8 + i]);
        }
        if ((mx - mn) > 1.0f) {
            const float ott = 1.0f / 255.0f;
            const float ubt = -10.0f / 255.0f;
            float otr = mx - 1.0f;
            float s1 = ott / (otr != 0.0f ? otr : 1.0f);
            float c1 = 1.0f - ott;
            float c2 = 1.0f - ubt;
            P1 = 255.0f * c1 * c2;
            P3 = 255.0f * s1 * c2;
            Q3 = 255.0f * c2 * (c1 - s1);
        }
    }

    // ---- stage B: vertical (height) resample, write transposed ----
    for (int t = tid; t < PAT_W * 8; t += 256) {
        int g  = t / PAT_W;
        int ic = t - g * PAT_W;
        int mb = g * 8;
        const float* p = &s_in[mb * PSTR + ic];
        float w0 = p[0 * PSTR], w1 = p[1 * PSTR], w2 = p[2 * PSTR];
        float w3 = p[3 * PSTR], w4 = p[4 * PSTR], w5 = p[5 * PSTR];
        float w6 = p[6 * PSTR], w7 = p[7 * PSTR], w8 = p[8 * PSTR];
        float* q = &s_ut[ic * USTR + 2 * mb];
        #pragma unroll
        for (int mm = 0; mm < 8; mm++) {
            q[2 * mm]     = EVEN8(w0, w1, w2, w3, w4, w5, w6, w7);
            q[2 * mm + 1] = ODD8(w1, w2, w3, w4, w5, w6, w7, w8);
            w0 = w1; w1 = w2; w2 = w3; w3 = w4;
            w4 = w5; w5 = w6; w6 = w7; w7 = w8;
            if (mm < 7) w8 = p[(mm + 9) * PSTR];
        }
    }
    __syncthreads();

    // ---- stage C: horizontal (width) resample + reduce / renorm+store ----
    const int orr = tid & (TILE_H - 1);   // output row within tile
    const int h   = tid >> 7;             // column half (0,1)

    // preload the full 24-value window (independent conflict-free LDS)
    float win[24];
    #pragma unroll
    for (int j = 0; j < 24; j++) win[j] = s_ut[(16 * h + j) * USTR + orr];

    float vmin = __int_as_float(0x7f800000);
    float vmax = -vmin;

    float* dst = nullptr;
    if (WRITE) {
        size_t row = (size_t)(blockIdx.y * TILE_H + orr);
        dst = out + ((size_t)bc * OUT_SZ + row) * OUT_SZ
            + blockIdx.x * TILE_W + h * 32;
    }

    float r0 = 0.f, r1 = 0.f;
    #pragma unroll
    for (int n = 0; n < 16; n++) {
        float e = EVEN8(win[n],     win[n + 1], win[n + 2], win[n + 3],
                        win[n + 4], win[n + 5], win[n + 6], win[n + 7]);
        float o = ODD8 (win[n + 1], win[n + 2], win[n + 3], win[n + 4],
                        win[n + 5], win[n + 6], win[n + 7], win[n + 8]);
        if (!WRITE) {
            vmin = fminf(vmin, fminf(e, o));
            vmax = fmaxf(vmax, fmaxf(e, o));
        } else {
            float fe = fminf(fminf(e * P1, fmaf(e, P3, Q3)), 255.0f);
            float fo = fminf(fminf(o * P1, fmaf(o, P3, Q3)), 255.0f);
            // cvt.rzi.u32 clamps negatives to 0; fminf clamped the top
            fe = (float)__float2uint_rz(fe);
            fo = (float)__float2uint_rz(fo);
            if (n & 1) {
                *reinterpret_cast<float4*>(dst + 2 * (n - 1)) =
                    make_float4(r0, r1, fe, fo);
            } else {
                r0 = fe; r1 = fo;
            }
        }
    }

    if (!WRITE) {
        #pragma unroll
        for (int m = 16; m; m >>= 1) {
            vmin = fminf(vmin, __shfl_xor_sync(0xffffffffu, vmin, m));
            vmax = fmaxf(vmax, __shfl_xor_sync(0xffffffffu, vmax, m));
        }
        int w = tid >> 5, l = tid & 31;
        if (l == 0) { s_red[w] = vmin; s_red[8 + w] = vmax; }
        __syncthreads();
        if (tid == 0) {
            float a = s_red[0], b = s_red[8];
            #pragma unroll
            for (int i = 1; i < 8; i++) {
                a = fminf(a, s_red[i]);
                b = fmaxf(b, s_red[8 + i]);
            }
            int slot = blockIdx.y * 16 + blockIdx.x;
            g_pmin[bc * SLOTS + slot] = a;
            g_pmax[bc * SLOTS + slot] = b;
        }
    }
}

extern "C" void kernel_launch(void* const* d_in, const int* in_sizes, int n_in,
                              void* d_out, int out_size)
{
    const float* x = (const float*)d_in[0];
    float* out = (float*)d_out;

    dim3 grid(OUT_SZ / TILE_W, OUT_SZ / TILE_H, NCH);
    k_resize<false><<<grid, 256>>>(x, nullptr);
    k_resize<true ><<<grid, 256>>>(x, out);
}

// round 8
// speedup vs baseline: 1.8823x; 1.3626x over previous
#include <cuda_runtime.h>
#include <cstdint>

// LanczosInterpolationLayer: x f32 [32,3,512,512] -> Lanczos4 2x upsample ->
// per-image range renormalize -> *255 -> uint8 (saturating trunc) -> f32 out.
//
// R7 (258us, pass2=180us, L1 74%): store wavefronts were the cap — per-warp
// STG.128 touched 32 lines (lanes = different output rows). R8:
//  - s_ut transposed to [orow][icol]: stage-C windows contiguous in smem.
//  - pass-2 stage C: thread = (row, 4-px segment), warp = 2 rows x 64 cols,
//    8 row-group iters -> one ideal-coalesced STG.128 per thread per iter
//    (4 lines/warp-instr, 8x fewer store wavefronts).
//  - pass-1 keeps full-row mapping (no stores), now with contiguous loads.

#define NIMG   32
#define NCH    96
#define IN_SZ  512
#define OUT_SZ 1024
#define TILE_W 64           // output cols per block
#define TILE_H 128          // output rows per block
#define PAT_W  40           // input patch cols (32 + 8 halo)
#define PAT_H  72           // input patch rows (64 + 8 halo)
#define PSTR   41           // s_in stride (odd -> conflict-free)
#define USTR   41           // s_ut stride: [orow 128][icol 40 pad 41]
#define SLOTS  128          // blocks per channel (16 x * 8 y)

__device__ float g_pmin[NCH * SLOTS];
__device__ float g_pmax[NCH * SLOTS];

// Normalized Lanczos4 weights, even phase (output 2m): tap j hits input m-4+j.
#define WE0 (-0.0039706f)
#define WE1 ( 0.0314676f)
#define WE2 (-0.0916620f)
#define WE3 ( 0.2826868f)
#define WE4 ( 0.8933939f)
#define WE5 (-0.1523043f)
#define WE6 ( 0.0554435f)
#define WE7 (-0.0150549f)

#define EVEN8(a0,a1,a2,a3,a4,a5,a6,a7) \
  fmaf((a7), WE7, fmaf((a6), WE6, fmaf((a5), WE5, fmaf((a4), WE4, \
  fmaf((a3), WE3, fmaf((a2), WE2, fmaf((a1), WE1, (a0) * WE0)))))))
#define ODD8(a1,a2,a3,a4,a5,a6,a7,a8) \
  fmaf((a8), WE0, fmaf((a7), WE1, fmaf((a6), WE2, fmaf((a5), WE3, \
  fmaf((a4), WE4, fmaf((a3), WE5, fmaf((a2), WE6, (a1) * WE7)))))))

template <bool WRITE>
__global__ void __launch_bounds__(256, 5)
k_resize(const float* __restrict__ x, float* __restrict__ out)
{
    __shared__ float s_in[PAT_H * PSTR];    // input patch  [irow][icol]
    __shared__ float s_ut[TILE_H * USTR];   // H-resampled  [orow][icol]
    __shared__ float s_red[16];

    const int tid = threadIdx.x;
    const int bc  = blockIdx.z;                  // image*3 + channel
    const int m0  = blockIdx.y * (TILE_H / 2);   // input row base
    const int n0  = blockIdx.x * (TILE_W / 2);   // input col base
    const float* src = x + (size_t)bc * (IN_SZ * IN_SZ);

    // ---- pass 2 only: reduce this image's 384 min/max partials ----
    if (WRITE) {
        const int img3 = (bc / 3) * 3;
        float a = __int_as_float(0x7f800000);
        float b = -a;
        #pragma unroll
        for (int i = 0; i < 2; i++) {
            int idx = tid + 256 * i;
            if (idx < 3 * SLOTS) {
                a = fminf(a, g_pmin[img3 * SLOTS + idx]);
                b = fmaxf(b, g_pmax[img3 * SLOTS + idx]);
            }
        }
        #pragma unroll
        for (int m = 16; m; m >>= 1) {
            a = fminf(a, __shfl_xor_sync(0xffffffffu, a, m));
            b = fmaxf(b, __shfl_xor_sync(0xffffffffu, b, m));
        }
        if ((tid & 31) == 0) {
            s_red[tid >> 5]       = a;
            s_red[8 + (tid >> 5)] = b;
        }
    }

    // ---- stage A: load input patch with replicate border ----
    #pragma unroll
    for (int i = 0; i < 12; i++) {
        int idx = tid + 256 * i;
        if (idx < PAT_H * PAT_W) {
            int r = idx / PAT_W;
            int c = idx - r * PAT_W;
            int gy = min(max(m0 - 4 + r, 0), IN_SZ - 1);
            int gx = min(max(n0 - 4 + c, 0), IN_SZ - 1);
            s_in[r * PSTR + c] = src[gy * IN_SZ + gx];
        }
    }
    __syncthreads();

    // renorm collapsed: f(v) = min(P1*v, P3*v + Q3), then clamp+trunc.
    float P1 = 255.f, P3 = 255.f, Q3 = 0.f;
    if (WRITE) {
        float mn = s_red[0], mx = s_red[8];
        #pragma unroll
        for (int i = 1; i < 8; i++) {
            mn = fminf(mn, s_red[i]);
            mx = fmaxf(mx, s_red[8 + i]);
        }
        if ((mx - mn) > 1.0f) {
            const float ott = 1.0f / 255.0f;
            const float ubt = -10.0f / 255.0f;
            float otr = mx - 1.0f;
            float s1 = ott / (otr != 0.0f ? otr : 1.0f);
            float c1 = 1.0f - ott;
            float c2 = 1.0f - ubt;
            P1 = 255.0f * c1 * c2;
            P3 = 255.0f * s1 * c2;
            Q3 = 255.0f * c2 * (c1 - s1);
        }
    }

    // ---- stage B: vertical (height) resample -> s_ut[orow][icol] ----
    for (int t = tid; t < PAT_W * 8; t += 256) {
        int g  = t / PAT_W;
        int ic = t - g * PAT_W;
        int mb = g * 8;
        const float* p = &s_in[mb * PSTR + ic];
        float w0 = p[0 * PSTR], w1 = p[1 * PSTR], w2 = p[2 * PSTR];
        float w3 = p[3 * PSTR], w4 = p[4 * PSTR], w5 = p[5 * PSTR];
        float w6 = p[6 * PSTR], w7 = p[7 * PSTR], w8 = p[8 * PSTR];
        float* q = &s_ut[2 * mb * USTR + ic];
        #pragma unroll
        for (int mm = 0; mm < 8; mm++) {
            q[(2 * mm)     * USTR] = EVEN8(w0, w1, w2, w3, w4, w5, w6, w7);
            q[(2 * mm + 1) * USTR] = ODD8(w1, w2, w3, w4, w5, w6, w7, w8);
            w0 = w1; w1 = w2; w2 = w3; w3 = w4;
            w4 = w5; w5 = w6; w6 = w7; w7 = w8;
            if (mm < 7) w8 = p[(mm + 9) * PSTR];
        }
    }
    __syncthreads();

    // ---- stage C ----
    if (!WRITE) {
        // full-row mapping: thread = (orow, col half); contiguous window
        const int orr = tid & (TILE_H - 1);
        const int h   = tid >> 7;
        const float* w = &s_ut[orr * USTR + 16 * h];

        float win[24];
        #pragma unroll
        for (int j = 0; j < 24; j++) win[j] = w[j];

        float vmin = __int_as_float(0x7f800000);
        float vmax = -vmin;
        #pragma unroll
        for (int n = 0; n < 16; n++) {
            float e = EVEN8(win[n],     win[n + 1], win[n + 2], win[n + 3],
                            win[n + 4], win[n + 5], win[n + 6], win[n + 7]);
            float o = ODD8 (win[n + 1], win[n + 2], win[n + 3], win[n + 4],
                            win[n + 5], win[n + 6], win[n + 7], win[n + 8]);
            vmin = fminf(vmin, fminf(e, o));
            vmax = fmaxf(vmax, fmaxf(e, o));
        }
        #pragma unroll
        for (int m = 16; m; m >>= 1) {
            vmin = fminf(vmin, __shfl_xor_sync(0xffffffffu, vmin, m));
            vmax = fmaxf(vmax, __shfl_xor_sync(0xffffffffu, vmax, m));
        }
        int w5 = tid >> 5, l = tid & 31;
        if (l == 0) { s_red[w5] = vmin; s_red[8 + w5] = vmax; }
        __syncthreads();
        if (tid == 0) {
            float a = s_red[0], b = s_red[8];
            #pragma unroll
            for (int i = 1; i < 8; i++) {
                a = fminf(a, s_red[i]);
                b = fmaxf(b, s_red[8 + i]);
            }
            int slot = blockIdx.y * 16 + blockIdx.x;
            g_pmin[bc * SLOTS + slot] = a;
            g_pmax[bc * SLOTS + slot] = b;
        }
    } else {
        // coalesced mapping: thread = (row, 4-px segment); warp = 2 rows.
        const int seg  = tid & 15;          // 16 segments * 4 px = 64 cols
        const int rsub = tid >> 4;          // 0..15 rows per iteration
        const int ic0  = 2 * seg;           // window start in s_ut cols
        float* dstb = out + ((size_t)bc * OUT_SZ + blockIdx.y * TILE_H + rsub)
                          * OUT_SZ + blockIdx.x * TILE_W + seg * 4;
        #pragma unroll 2
        for (int it = 0; it < 8; it++) {
            const float* w = &s_ut[(it * 16 + rsub) * USTR + ic0];
            float w0 = w[0], w1 = w[1], w2 = w[2], w3 = w[3], w4 = w[4],
                  w5 = w[5], w6 = w[6], w7 = w[7], w8 = w[8], w9 = w[9];
            float p0 = EVEN8(w0, w1, w2, w3, w4, w5, w6, w7);
            float p1 = ODD8 (w1, w2, w3, w4, w5, w6, w7, w8);
            float p2 = EVEN8(w1, w2, w3, w4, w5, w6, w7, w8);
            float p3 = ODD8 (w2, w3, w4, w5, w6, w7, w8, w9);
            float f0 = fminf(fminf(p0 * P1, fmaf(p0, P3, Q3)), 255.0f);
            float f1 = fminf(fminf(p1 * P1, fmaf(p1, P3, Q3)), 255.0f);
            float f2 = fminf(fminf(p2 * P1, fmaf(p2, P3, Q3)), 255.0f);
            float f3 = fminf(fminf(p3 * P1, fmaf(p3, P3, Q3)), 255.0f);
            // cvt.rzi.u32 clamps negatives to 0; fminf clamped the top
            f0 = (float)__float2uint_rz(f0);
            f1 = (float)__float2uint_rz(f1);
            f2 = (float)__float2uint_rz(f2);
            f3 = (float)__float2uint_rz(f3);
            *reinterpret_cast<float4*>(dstb + (size_t)it * 16 * OUT_SZ) =
                make_float4(f0, f1, f2, f3);
        }
    }
}

extern "C" void kernel_launch(void* const* d_in, const int* in_sizes, int n_in,
                              void* d_out, int out_size)
{
    const float* x = (const float*)d_in[0];
    float* out = (float*)d_out;

    dim3 grid(OUT_SZ / TILE_W, OUT_SZ / TILE_H, NCH);
    k_resize<false><<<grid, 256>>>(x, nullptr);
    k_resize<true ><<<grid, 256>>>(x, out);
}